// round 6
// baseline (speedup 1.0000x reference)
#include <cuda_runtime.h>

// GaussianSampler: R[b,c] = sum_{y,x} X[b,c,y,x] * gx[c,x] * gy[c,y] / norm
// R6: one block per 2 ADJACENT channels (32 KiB contiguous stream). Halves
// per-byte prologue/epilogue overhead vs R1 without R2's occupancy collapse:
//  - prologue uses all 256 threads (1 expf each: gx/gy for both channels)
//  - loads remain two sequential 4-batches (no 8-wide reg blow-up)
//  - single fused epilogue for both channels
// __launch_bounds__(256,8) pins regs<=32 -> occ stays ~90%.

#define NCH 1024
#define HH  64
#define WW  64

__global__ __launch_bounds__(256, 8)
void gaussian_sampler_kernel(
    const float* __restrict__ X,     // [B, C, H, W]
    const float* __restrict__ wx,    // [C]
    const float* __restrict__ wy,    // [C]
    const float* __restrict__ wsx,   // [C]
    const float* __restrict__ wsy,   // [C]
    float* __restrict__ out)         // [B, C]
{
    const int blk = blockIdx.x;            // 16384 blocks
    const int c0  = (blk & 511) * 2;       // first of 2 adjacent channels
    const int t   = threadIdx.x;

    __shared__ float gxs[2][WW];
    __shared__ float gys[2][HH];           // norm folded in
    __shared__ float red[2][8];

    // ---- prologue: all 256 threads compute exactly one weight ----
    // t in [0,64):    gx, channel c0
    // t in [64,128):  gy, channel c0
    // t in [128,192): gx, channel c0+1
    // t in [192,256): gy, channel c0+1
    {
        const int ch  = t >> 7;            // 0 or 1
        const int hi  = (t >> 6) & 1;      // 0 = gx, 1 = gy
        const int i   = t & 63;
        const int c   = c0 + ch;
        const float coord = -0.984375f + (float)i * 0.03125f;
        if (hi == 0) {
            float s = wsx[c];
            float d = coord - wx[c];
            gxs[ch][i] = __expf(-d * d / (2.0f * s * s));
        } else {
            float sy = wsy[c];
            float sx = wsx[c];
            float d = coord - wy[c];
            float scale = 1.0f / (2.5066282746310002f * sx * sy * 1024.0f);
            gys[ch][i] = __expf(-d * d / (2.0f * sy * sy)) * scale;
        }
    }
    __syncthreads();

    // ---- stream 32 KiB: 2048 float4, thread t takes j = t + 256k ----
    const float4* __restrict__ xp = reinterpret_cast<const float4*>(
        X + (size_t)blk * (2 * HH * WW));

    // Per thread: x = (4t)&63 invariant; y = (4t>>6) + 16k (k within channel).
    const int x  = (4 * t) & 63;
    const int y0 = (4 * t) >> 6;

    float acc0 = 0.0f, acc1 = 0.0f;

    // channel c0: k = 0..3
    {
        float4 v0 = xp[t];
        float4 v1 = xp[t + 256];
        float4 v2 = xp[t + 512];
        float4 v3 = xp[t + 768];
        float4 g = *reinterpret_cast<const float4*>(&gxs[0][x]);
        acc0  = gys[0][y0]      * (v0.x*g.x + v0.y*g.y + v0.z*g.z + v0.w*g.w);
        acc0 += gys[0][y0 + 16] * (v1.x*g.x + v1.y*g.y + v1.z*g.z + v1.w*g.w);
        acc0 += gys[0][y0 + 32] * (v2.x*g.x + v2.y*g.y + v2.z*g.z + v2.w*g.w);
        acc0 += gys[0][y0 + 48] * (v3.x*g.x + v3.y*g.y + v3.z*g.z + v3.w*g.w);
    }
    // channel c0+1: k = 4..7
    {
        float4 v0 = xp[t + 1024];
        float4 v1 = xp[t + 1280];
        float4 v2 = xp[t + 1536];
        float4 v3 = xp[t + 1792];
        float4 g = *reinterpret_cast<const float4*>(&gxs[1][x]);
        acc1  = gys[1][y0]      * (v0.x*g.x + v0.y*g.y + v0.z*g.z + v0.w*g.w);
        acc1 += gys[1][y0 + 16] * (v1.x*g.x + v1.y*g.y + v1.z*g.z + v1.w*g.w);
        acc1 += gys[1][y0 + 32] * (v2.x*g.x + v2.y*g.y + v2.z*g.z + v2.w*g.w);
        acc1 += gys[1][y0 + 48] * (v3.x*g.x + v3.y*g.y + v3.z*g.z + v3.w*g.w);
    }

    // ---- fused reduction for both channels ----
    #pragma unroll
    for (int off = 16; off > 0; off >>= 1) {
        acc0 += __shfl_down_sync(0xffffffffu, acc0, off);
        acc1 += __shfl_down_sync(0xffffffffu, acc1, off);
    }
    if ((t & 31) == 0) {
        red[0][t >> 5] = acc0;
        red[1][t >> 5] = acc1;
    }
    __syncthreads();

    // 16 threads: thread t -> channel g = t>>3, slot = t&7
    if (t < 16) {
        float v = red[t >> 3][t & 7];
        v += __shfl_down_sync(0x0000ffffu, v, 4, 8);
        v += __shfl_down_sync(0x0000ffffu, v, 2, 8);
        v += __shfl_down_sync(0x0000ffffu, v, 1, 8);
        if ((t & 7) == 0) {
            // out index = b*NCH + c0 + (t>>3); blk*2 = b*NCH + c0
            out[blk * 2 + (t >> 3)] = v;
        }
    }
}

extern "C" void kernel_launch(void* const* d_in, const int* in_sizes, int n_in,
                              void* d_out, int out_size) {
    // metadata order: X, wx, wy, wsigmax, wsigmay, mask
    const float* X   = (const float*)d_in[0];
    const float* wx  = (const float*)d_in[1];
    const float* wy  = (const float*)d_in[2];
    const float* wsx = (const float*)d_in[3];
    const float* wsy = (const float*)d_in[4];
    // mask (d_in[5]) is all-true by construction; nonzero(size=C) gather is identity.
    float* out = (float*)d_out;

    const int B = in_sizes[0] / (NCH * HH * WW);   // 32
    const int nblocks = B * NCH / 2;               // 16384

    gaussian_sampler_kernel<<<nblocks, 256>>>(X, wx, wy, wsx, wsy, out);
}

// round 7
// speedup vs baseline: 1.0049x; 1.0049x over previous
#include <cuda_runtime.h>

// GaussianSampler: R[b,c] = sum_{y,x} X[b,c,y,x] * gx[c,x] * gy[c,y] / norm
// R7 = R1 (best: 77.4us) with streaming loads (__ldcs, evict-first).
// X is a strict use-once 512 MiB stream through a 126 MB L2; evict-first
// removes dead-line churn from the LTS path, the identified chip-level cap.

#define NCH 1024
#define HH  64
#define WW  64

__global__ __launch_bounds__(256, 8)
void gaussian_sampler_kernel(
    const float* __restrict__ X,     // [B, C, H, W]
    const float* __restrict__ wx,    // [C]
    const float* __restrict__ wy,    // [C]
    const float* __restrict__ wsx,   // [C]
    const float* __restrict__ wsy,   // [C]
    float* __restrict__ out)         // [B, C]
{
    const int blk = blockIdx.x;          // = b*NCH + c
    const int c   = blk & (NCH - 1);
    const int t   = threadIdx.x;

    __shared__ float gx[WW];
    __shared__ float gy[HH];             // norm scale folded in
    __shared__ float red[8];

    // coord[i] = linspace(-63/64, 63/64, 64)[i] = -0.984375 + i/32
    if (t < 64) {
        float s = wsx[c];
        float d = (-0.984375f + (float)t * 0.03125f) - wx[c];
        gx[t] = __expf(-d * d / (2.0f * s * s));
    } else if (t < 128) {
        int i = t - 64;
        float sy = wsy[c];
        float sx = wsx[c];
        float d = (-0.984375f + (float)i * 0.03125f) - wy[c];
        // fold 1/(sqrt(2pi)*sx*sy*1024) into gy
        float scale = 1.0f / (2.5066282746310002f * sx * sy * 1024.0f);
        gy[i] = __expf(-d * d / (2.0f * sy * sy)) * scale;
    }
    __syncthreads();

    const float4* __restrict__ xp =
        reinterpret_cast<const float4*>(X + (size_t)blk * (HH * WW));

    float acc = 0.0f;
    #pragma unroll
    for (int it = 0; it < 4; it++) {
        int j = t + it * 256;            // float4 index in [0, 1024)
        float4 v = __ldcs(&xp[j]);       // streaming: evict-first
        int lin = j << 2;
        int y = lin >> 6;
        int x = lin & 63;
        float gyv = gy[y];
        acc += gyv * (v.x * gx[x] + v.y * gx[x + 1] +
                      v.z * gx[x + 2] + v.w * gx[x + 3]);
    }

    // Intra-warp reduce
    #pragma unroll
    for (int off = 16; off > 0; off >>= 1)
        acc += __shfl_down_sync(0xffffffffu, acc, off);

    if ((t & 31) == 0) red[t >> 5] = acc;
    __syncthreads();

    if (t < 8) {
        float v = red[t];
        #pragma unroll
        for (int off = 4; off > 0; off >>= 1)
            v += __shfl_down_sync(0x000000ffu, v, off);
        if (t == 0) out[blk] = v;
    }
}

extern "C" void kernel_launch(void* const* d_in, const int* in_sizes, int n_in,
                              void* d_out, int out_size) {
    // metadata order: X, wx, wy, wsigmax, wsigmay, mask
    const float* X   = (const float*)d_in[0];
    const float* wx  = (const float*)d_in[1];
    const float* wy  = (const float*)d_in[2];
    const float* wsx = (const float*)d_in[3];
    const float* wsy = (const float*)d_in[4];
    // mask (d_in[5]) is all-true by construction; nonzero(size=C) gather is identity.
    float* out = (float*)d_out;

    const int B = in_sizes[0] / (NCH * HH * WW);   // 32
    const int nblocks = B * NCH;                   // 32768

    gaussian_sampler_kernel<<<nblocks, 256>>>(X, wx, wy, wsx, wsy, out);
}